// round 1
// baseline (speedup 1.0000x reference)
#include <cuda_runtime.h>
#include <math.h>

// Problem constants
#define BB 2
#define TT 2048
#define CC 1024
#define HH 16
#define HS 64
// M for token-major GEMMs
#define MM (BB*TT)       // 4096

// Scratch (device globals: allocation-free)
__device__ float g_q[BB*HH*TT*HS];     // [B,H,T,HS]
__device__ float g_k[BB*HH*TT*HS];
__device__ float g_v[BB*HH*TT*HS];
__device__ float g_y[BB*TT*CC];        // [B,T,C] attention output
__device__ float g_cos[TT*32];
__device__ float g_sin[TT*32];

// ---------------------------------------------------------------------------
// RoPE tables: cos/sin(t * theta^{-i/32}) for i in [0,32)
// Match JAX: inv_freq and freqs rounded to f32, then accurate trig on that.
// ---------------------------------------------------------------------------
__global__ void rope_tables_kernel() {
    int idx = blockIdx.x * blockDim.x + threadIdx.x;   // t*32 + i
    if (idx >= TT * 32) return;
    int i = idx & 31;
    int t = idx >> 5;
    double invf_d = exp(-(double)i * (log(10000.0) / 32.0));
    float invf = (float)invf_d;                 // f32 inv_freq (as reference)
    float arg_f = (float)t * invf;              // f32 freqs (as reference)
    double s, c;
    sincos((double)arg_f, &s, &c);              // accurate trig on f32 arg
    g_cos[idx] = (float)c;
    g_sin[idx] = (float)s;
}

// ---------------------------------------------------------------------------
// QKV projection GEMM: X[4096,1024] @ W[1024,1024] + b
// 64x64 block tile, BK=32, 256 threads, 4x4 micro-tile.
// Epilogue writes [B,H,T,HS] layout. blockIdx.z selects Q/K/V.
// ---------------------------------------------------------------------------
__global__ void __launch_bounds__(256) qkv_gemm_kernel(
    const float* __restrict__ X,
    const float* __restrict__ wq, const float* __restrict__ wk, const float* __restrict__ wv,
    const float* __restrict__ bq, const float* __restrict__ bk, const float* __restrict__ bv)
{
    const int N = CC, K = CC;
    int which = blockIdx.z;
    const float* W    = (which == 0) ? wq : (which == 1) ? wk : wv;
    const float* bias = (which == 0) ? bq : (which == 1) ? bk : bv;
    float* out        = (which == 0) ? g_q : (which == 1) ? g_k : g_v;

    __shared__ float As[64][33];
    __shared__ float Bs[32][65];

    int m0 = blockIdx.x * 64;
    int n0 = blockIdx.y * 64;
    int tid = threadIdx.x;
    int tx = tid & 15, ty = tid >> 4;

    float acc[4][4] = {};

    int ar  = tid >> 2;           // 0..63
    int ac4 = (tid & 3) * 4;      // 0,4,8,12
    int br  = tid >> 4;           // 0..15
    int bc4 = (tid & 15) * 4;     // 0..60

    for (int k0 = 0; k0 < K; k0 += 32) {
        float4 a0 = *(const float4*)&X[(m0 + ar) * K + k0 + ac4];
        float4 a1 = *(const float4*)&X[(m0 + ar) * K + k0 + ac4 + 16];
        float4 b0 = *(const float4*)&W[(k0 + br) * N + n0 + bc4];
        float4 b1 = *(const float4*)&W[(k0 + br + 16) * N + n0 + bc4];
        As[ar][ac4 + 0]  = a0.x; As[ar][ac4 + 1]  = a0.y;
        As[ar][ac4 + 2]  = a0.z; As[ar][ac4 + 3]  = a0.w;
        As[ar][ac4 + 16] = a1.x; As[ar][ac4 + 17] = a1.y;
        As[ar][ac4 + 18] = a1.z; As[ar][ac4 + 19] = a1.w;
        Bs[br][bc4 + 0] = b0.x; Bs[br][bc4 + 1] = b0.y;
        Bs[br][bc4 + 2] = b0.z; Bs[br][bc4 + 3] = b0.w;
        Bs[br + 16][bc4 + 0] = b1.x; Bs[br + 16][bc4 + 1] = b1.y;
        Bs[br + 16][bc4 + 2] = b1.z; Bs[br + 16][bc4 + 3] = b1.w;
        __syncthreads();
        #pragma unroll
        for (int kk = 0; kk < 32; kk++) {
            float av[4], bv2[4];
            #pragma unroll
            for (int ii = 0; ii < 4; ii++) av[ii]  = As[ty * 4 + ii][kk];
            #pragma unroll
            for (int jj = 0; jj < 4; jj++) bv2[jj] = Bs[kk][tx * 4 + jj];
            #pragma unroll
            for (int ii = 0; ii < 4; ii++)
                #pragma unroll
                for (int jj = 0; jj < 4; jj++)
                    acc[ii][jj] += av[ii] * bv2[jj];
        }
        __syncthreads();
    }

    #pragma unroll
    for (int ii = 0; ii < 4; ii++) {
        int m = m0 + ty * 4 + ii;
        int b = m >> 11, t = m & (TT - 1);
        #pragma unroll
        for (int jj = 0; jj < 4; jj++) {
            int n = n0 + tx * 4 + jj;
            int h = n >> 6, d = n & 63;
            out[(((b * HH + h) * TT) + t) * HS + d] = acc[ii][jj] + bias[n];
        }
    }
}

// ---------------------------------------------------------------------------
// RoPE apply (in place on g_q, g_k). One thread per (bh, t, pair-index i).
// ---------------------------------------------------------------------------
__global__ void rope_apply_kernel() {
    int idx = blockIdx.x * blockDim.x + threadIdx.x;   // BB*HH*TT*32 = 2^21
    if (idx >= BB * HH * TT * 32) return;
    int i  = idx & 31;
    int t  = (idx >> 5) & (TT - 1);
    int bh = idx >> 16;                                 // TT*32 = 65536
    float c = g_cos[(t << 5) + i];
    float s = g_sin[(t << 5) + i];
    int base = (bh * TT + t) * HS + i;
    float q1 = g_q[base], q2 = g_q[base + 32];
    g_q[base]      = q1 * c - q2 * s;
    g_q[base + 32] = q2 * c + q1 * s;
    float k1 = g_k[base], k2 = g_k[base + 32];
    g_k[base]      = k1 * c - k2 * s;
    g_k[base + 32] = k2 * c + k1 * s;
}

// ---------------------------------------------------------------------------
// Flash-style causal attention.
// grid = (T/64, B*H), 256 threads (16x16). BLOCK_M=64, BLOCK_N=32, D=64.
// Each thread: 4 q-rows (ty) x {2 S-cols | 4 O-dims} (tx).
// ---------------------------------------------------------------------------
__global__ void __launch_bounds__(256) flash_attn_kernel() {
    __shared__ float Qs[64][65];
    __shared__ float Ks[32][65];
    __shared__ float Vs[32][64];
    __shared__ float Ps[64][33];

    int qb = blockIdx.x;
    int bh = blockIdx.y;
    int q0 = qb * 64;
    const float* Qp = g_q + (size_t)bh * TT * HS;
    const float* Kp = g_k + (size_t)bh * TT * HS;
    const float* Vp = g_v + (size_t)bh * TT * HS;

    int tid = threadIdx.x;
    int tx = tid & 15, ty = tid >> 4;

    // Load Q tile (scaled by 1/sqrt(HS))
    #pragma unroll
    for (int r = 0; r < 4; r++) {
        int e4  = tid + r * 256;          // 0..1023 float4s
        int row = e4 >> 4;
        int c4  = (e4 & 15) * 4;
        float4 qv = *(const float4*)&Qp[(q0 + row) * HS + c4];
        Qs[row][c4 + 0] = qv.x * 0.125f;
        Qs[row][c4 + 1] = qv.y * 0.125f;
        Qs[row][c4 + 2] = qv.z * 0.125f;
        Qs[row][c4 + 3] = qv.w * 0.125f;
    }

    float mrow[4], lrow[4], acc[4][4];
    #pragma unroll
    for (int ii = 0; ii < 4; ii++) {
        mrow[ii] = -1e30f;
        lrow[ii] = 0.f;
        #pragma unroll
        for (int dd = 0; dd < 4; dd++) acc[ii][dd] = 0.f;
    }
    __syncthreads();

    int ktmax = qb * 2 + 1;
    for (int kt = 0; kt <= ktmax; kt++) {
        int k0 = kt * 32;
        // Load K,V tiles (32x64 each)
        #pragma unroll
        for (int r = 0; r < 2; r++) {
            int e4  = tid + r * 256;      // 0..511 float4s
            int row = e4 >> 4;
            int c4  = (e4 & 15) * 4;
            float4 kv = *(const float4*)&Kp[(k0 + row) * HS + c4];
            float4 vv = *(const float4*)&Vp[(k0 + row) * HS + c4];
            Ks[row][c4 + 0] = kv.x; Ks[row][c4 + 1] = kv.y;
            Ks[row][c4 + 2] = kv.z; Ks[row][c4 + 3] = kv.w;
            Vs[row][c4 + 0] = vv.x; Vs[row][c4 + 1] = vv.y;
            Vs[row][c4 + 2] = vv.z; Vs[row][c4 + 3] = vv.w;
        }
        __syncthreads();

        // S = Q @ K^T  (this thread: rows ty*4+ii, cols tx*2+jj)
        float s[4][2];
        #pragma unroll
        for (int ii = 0; ii < 4; ii++) { s[ii][0] = 0.f; s[ii][1] = 0.f; }
        #pragma unroll
        for (int d = 0; d < 64; d++) {
            float av[4], bv2[2];
            #pragma unroll
            for (int ii = 0; ii < 4; ii++) av[ii]  = Qs[ty * 4 + ii][d];
            bv2[0] = Ks[tx * 2 + 0][d];
            bv2[1] = Ks[tx * 2 + 1][d];
            #pragma unroll
            for (int ii = 0; ii < 4; ii++) {
                s[ii][0] += av[ii] * bv2[0];
                s[ii][1] += av[ii] * bv2[1];
            }
        }

        // Causal mask
        #pragma unroll
        for (int ii = 0; ii < 4; ii++) {
            int qi = q0 + ty * 4 + ii;
            #pragma unroll
            for (int jj = 0; jj < 2; jj++) {
                int kj = k0 + tx * 2 + jj;
                if (kj > qi) s[ii][jj] = -1e30f;
            }
        }

        // Online softmax (row reductions over the 16-lane tx group)
        #pragma unroll
        for (int ii = 0; ii < 4; ii++) {
            float r = fmaxf(s[ii][0], s[ii][1]);
            #pragma unroll
            for (int off = 8; off > 0; off >>= 1)
                r = fmaxf(r, __shfl_xor_sync(0xffffffffu, r, off));
            float mnew = fmaxf(mrow[ii], r);
            float p0 = __expf(s[ii][0] - mnew);
            float p1 = __expf(s[ii][1] - mnew);
            float rs = p0 + p1;
            #pragma unroll
            for (int off = 8; off > 0; off >>= 1)
                rs += __shfl_xor_sync(0xffffffffu, rs, off);
            float f = __expf(mrow[ii] - mnew);
            lrow[ii] = lrow[ii] * f + rs;
            mrow[ii] = mnew;
            #pragma unroll
            for (int dd = 0; dd < 4; dd++) acc[ii][dd] *= f;
            Ps[ty * 4 + ii][tx * 2 + 0] = p0;
            Ps[ty * 4 + ii][tx * 2 + 1] = p1;
        }
        __syncthreads();

        // O += P @ V  (this thread: rows ty*4+ii, dims tx*4+dd)
        #pragma unroll
        for (int j = 0; j < 32; j++) {
            float pv[4], vv[4];
            #pragma unroll
            for (int ii = 0; ii < 4; ii++) pv[ii] = Ps[ty * 4 + ii][j];
            #pragma unroll
            for (int dd = 0; dd < 4; dd++) vv[dd] = Vs[j][tx * 4 + dd];
            #pragma unroll
            for (int ii = 0; ii < 4; ii++)
                #pragma unroll
                for (int dd = 0; dd < 4; dd++)
                    acc[ii][dd] += pv[ii] * vv[dd];
        }
        __syncthreads();
    }

    // Write O back in [B,T,C] layout
    int b = bh >> 4, h = bh & 15;
    #pragma unroll
    for (int ii = 0; ii < 4; ii++) {
        int t = q0 + ty * 4 + ii;
        float inv = 1.f / lrow[ii];
        #pragma unroll
        for (int dd = 0; dd < 4; dd++) {
            int col = h * HS + tx * 4 + dd;
            g_y[((size_t)b * TT + t) * CC + col] = acc[ii][dd] * inv;
        }
    }
}

// ---------------------------------------------------------------------------
// Output projection: g_y[4096,1024] @ wc[1024,1024] + bc -> d_out
// ---------------------------------------------------------------------------
__global__ void __launch_bounds__(256) out_gemm_kernel(
    const float* __restrict__ W, const float* __restrict__ bias,
    float* __restrict__ out)
{
    const int N = CC, K = CC;
    const float* X = g_y;

    __shared__ float As[64][33];
    __shared__ float Bs[32][65];

    int m0 = blockIdx.x * 64;
    int n0 = blockIdx.y * 64;
    int tid = threadIdx.x;
    int tx = tid & 15, ty = tid >> 4;

    float acc[4][4] = {};

    int ar  = tid >> 2;
    int ac4 = (tid & 3) * 4;
    int br  = tid >> 4;
    int bc4 = (tid & 15) * 4;

    for (int k0 = 0; k0 < K; k0 += 32) {
        float4 a0 = *(const float4*)&X[(m0 + ar) * K + k0 + ac4];
        float4 a1 = *(const float4*)&X[(m0 + ar) * K + k0 + ac4 + 16];
        float4 b0 = *(const float4*)&W[(k0 + br) * N + n0 + bc4];
        float4 b1 = *(const float4*)&W[(k0 + br + 16) * N + n0 + bc4];
        As[ar][ac4 + 0]  = a0.x; As[ar][ac4 + 1]  = a0.y;
        As[ar][ac4 + 2]  = a0.z; As[ar][ac4 + 3]  = a0.w;
        As[ar][ac4 + 16] = a1.x; As[ar][ac4 + 17] = a1.y;
        As[ar][ac4 + 18] = a1.z; As[ar][ac4 + 19] = a1.w;
        Bs[br][bc4 + 0] = b0.x; Bs[br][bc4 + 1] = b0.y;
        Bs[br][bc4 + 2] = b0.z; Bs[br][bc4 + 3] = b0.w;
        Bs[br + 16][bc4 + 0] = b1.x; Bs[br + 16][bc4 + 1] = b1.y;
        Bs[br + 16][bc4 + 2] = b1.z; Bs[br + 16][bc4 + 3] = b1.w;
        __syncthreads();
        #pragma unroll
        for (int kk = 0; kk < 32; kk++) {
            float av[4], bv2[4];
            #pragma unroll
            for (int ii = 0; ii < 4; ii++) av[ii]  = As[ty * 4 + ii][kk];
            #pragma unroll
            for (int jj = 0; jj < 4; jj++) bv2[jj] = Bs[kk][tx * 4 + jj];
            #pragma unroll
            for (int ii = 0; ii < 4; ii++)
                #pragma unroll
                for (int jj = 0; jj < 4; jj++)
                    acc[ii][jj] += av[ii] * bv2[jj];
        }
        __syncthreads();
    }

    #pragma unroll
    for (int ii = 0; ii < 4; ii++) {
        int m = m0 + ty * 4 + ii;
        #pragma unroll
        for (int jj = 0; jj < 4; jj++) {
            int n = n0 + tx * 4 + jj;
            out[(size_t)m * N + n] = acc[ii][jj] + bias[n];
        }
    }
}

// ---------------------------------------------------------------------------
extern "C" void kernel_launch(void* const* d_in, const int* in_sizes, int n_in,
                              void* d_out, int out_size) {
    const float* qx = (const float*)d_in[0];
    const float* wq = (const float*)d_in[1];
    const float* bq = (const float*)d_in[2];
    const float* wk = (const float*)d_in[3];
    const float* bk = (const float*)d_in[4];
    const float* wv = (const float*)d_in[5];
    const float* bv = (const float*)d_in[6];
    const float* wc = (const float*)d_in[7];
    const float* bc = (const float*)d_in[8];
    float* out = (float*)d_out;

    rope_tables_kernel<<<(TT * 32 + 255) / 256, 256>>>();
    qkv_gemm_kernel<<<dim3(MM / 64, CC / 64, 3), 256>>>(qx, wq, wk, wv, bq, bk, bv);
    rope_apply_kernel<<<(BB * HH * TT * 32 + 255) / 256, 256>>>();
    flash_attn_kernel<<<dim3(TT / 64, BB * HH), 256>>>();
    out_gemm_kernel<<<dim3(MM / 64, CC / 64), 256>>>(wc, bc, out);
}

// round 3
// speedup vs baseline: 1.6087x; 1.6087x over previous
#include <cuda_runtime.h>
#include <cuda_bf16.h>
#include <math.h>
#include <stdint.h>

// Problem constants
#define BB 2
#define TT 2048
#define CC 1024
#define HH 16
#define HS 64
#define MM (BB*TT)       // 4096

// GEMM tiling (mma.sync bf16)
#define CTA_M 128
#define CTA_N 128
#define KSTG  32                 // K elems per smem stage
#define NS    (CC/KSTG)          // 32 stages
#define ASTR  40                 // smem row stride in bf16 elems (80B, conflict-free ldmatrix)

// Scratch (device globals: allocation-free)
__device__ float g_q[BB*HH*TT*HS];     // [B,H,T,HS]
__device__ float g_k[BB*HH*TT*HS];
__device__ float g_v[BB*HH*TT*HS];
__device__ float g_y[BB*TT*CC];        // [B,T,C] attention output
__device__ float g_cos[TT*32];
__device__ float g_sin[TT*32];

// bf16 hi/lo split staging
__device__ __nv_bfloat16 g_xhi[MM*CC];
__device__ __nv_bfloat16 g_xlo[MM*CC];
__device__ __nv_bfloat16 g_yhi[MM*CC];
__device__ __nv_bfloat16 g_ylo[MM*CC];
__device__ __nv_bfloat16 g_wthi[4*CC*CC];   // transposed [n][k]: wq,wk,wv,wc
__device__ __nv_bfloat16 g_wtlo[4*CC*CC];

// ---------------------------------------------------------------------------
// PTX helpers (family-wide sm_80+ instructions only; NO 'a'-gated features)
// ---------------------------------------------------------------------------
__device__ __forceinline__ uint32_t smem_u32(const void* p) {
    uint32_t a;
    asm("{ .reg .u64 t; cvta.to.shared.u64 t, %1; cvt.u32.u64 %0, t; }" : "=r"(a) : "l"(p));
    return a;
}
__device__ __forceinline__ void ldsm_x4(uint32_t* r, uint32_t addr) {
    asm volatile("ldmatrix.sync.aligned.m8n8.x4.shared.b16 {%0,%1,%2,%3}, [%4];"
        : "=r"(r[0]), "=r"(r[1]), "=r"(r[2]), "=r"(r[3]) : "r"(addr));
}
__device__ __forceinline__ void ldsm_x2(uint32_t* r, uint32_t addr) {
    asm volatile("ldmatrix.sync.aligned.m8n8.x2.shared.b16 {%0,%1}, [%2];"
        : "=r"(r[0]), "=r"(r[1]) : "r"(addr));
}
__device__ __forceinline__ void mma_bf16(float* c, const uint32_t* a, const uint32_t* b) {
    asm volatile(
        "mma.sync.aligned.m16n8k16.row.col.f32.bf16.bf16.f32 "
        "{%0,%1,%2,%3}, {%4,%5,%6,%7}, {%8,%9}, {%0,%1,%2,%3};"
        : "+f"(c[0]), "+f"(c[1]), "+f"(c[2]), "+f"(c[3])
        : "r"(a[0]), "r"(a[1]), "r"(a[2]), "r"(a[3]), "r"(b[0]), "r"(b[1]));
}

// ---------------------------------------------------------------------------
// RoPE tables
// ---------------------------------------------------------------------------
__global__ void rope_tables_kernel() {
    int idx = blockIdx.x * blockDim.x + threadIdx.x;   // t*32 + i
    if (idx >= TT * 32) return;
    int i = idx & 31;
    int t = idx >> 5;
    double invf_d = exp(-(double)i * (log(10000.0) / 32.0));
    float invf = (float)invf_d;
    float arg_f = (float)t * invf;
    double s, c;
    sincos((double)arg_f, &s, &c);
    g_cos[idx] = (float)c;
    g_sin[idx] = (float)s;
}

// ---------------------------------------------------------------------------
// fp32 -> bf16 hi/lo split (row-major passthrough), vectorized x4
// ---------------------------------------------------------------------------
__global__ void split_bf16_kernel(const float* __restrict__ src,
                                  __nv_bfloat16* __restrict__ hi,
                                  __nv_bfloat16* __restrict__ lo, int n4) {
    int i = blockIdx.x * blockDim.x + threadIdx.x;
    if (i >= n4) return;
    float4 v = ((const float4*)src)[i];
    float vv[4] = {v.x, v.y, v.z, v.w};
    __nv_bfloat162 h01, h23, l01, l23;
    __nv_bfloat16 h[4], l[4];
    #pragma unroll
    for (int j = 0; j < 4; j++) {
        h[j] = __float2bfloat16(vv[j]);
        l[j] = __float2bfloat16(vv[j] - __bfloat162float(h[j]));
    }
    h01.x = h[0]; h01.y = h[1]; h23.x = h[2]; h23.y = h[3];
    l01.x = l[0]; l01.y = l[1]; l23.x = l[2]; l23.y = l[3];
    ((__nv_bfloat162*)hi)[2*i]   = h01;
    ((__nv_bfloat162*)hi)[2*i+1] = h23;
    ((__nv_bfloat162*)lo)[2*i]   = l01;
    ((__nv_bfloat162*)lo)[2*i+1] = l23;
}

// ---------------------------------------------------------------------------
// Weight transpose + split: Wt[n][k] = split(W[k][n]); grid.z selects matrix
// ---------------------------------------------------------------------------
__global__ void wt_split_kernel(const float* __restrict__ wq, const float* __restrict__ wk,
                                const float* __restrict__ wv, const float* __restrict__ wc) {
    __shared__ float tile[32][33];
    int wsel = blockIdx.z;
    const float* W = (wsel == 0) ? wq : (wsel == 1) ? wk : (wsel == 2) ? wv : wc;
    __nv_bfloat16* Whi = g_wthi + (size_t)wsel * CC * CC;
    __nv_bfloat16* Wlo = g_wtlo + (size_t)wsel * CC * CC;
    int k0 = blockIdx.x * 32, n0 = blockIdx.y * 32;
    int tx = threadIdx.x, ty = threadIdx.y;   // (32,8)
    #pragma unroll
    for (int j = 0; j < 4; j++)
        tile[ty + 8*j][tx] = W[(size_t)(k0 + ty + 8*j) * CC + n0 + tx];
    __syncthreads();
    #pragma unroll
    for (int j = 0; j < 4; j++) {
        float v = tile[tx][ty + 8*j];
        __nv_bfloat16 h = __float2bfloat16(v);
        __nv_bfloat16 l = __float2bfloat16(v - __bfloat162float(h));
        size_t o = (size_t)(n0 + ty + 8*j) * CC + k0 + tx;
        Whi[o] = h;
        Wlo[o] = l;
    }
}

// ---------------------------------------------------------------------------
// mma.sync bf16 GEMM with 3-MMA split: D = A @ B^T (+bias), B stored [n][k].
// CTA 128x128, 8 warps in 2(m) x 4(n), warp tile 64x32, K staged 32.
// qkv_mode=1: epilogue -> g_q/g_k/g_v [B,H,T,HS]; else -> o_direct [m][n].
// ---------------------------------------------------------------------------
__global__ void __launch_bounds__(256, 1) gemm_mma_kernel(
    const __nv_bfloat16* __restrict__ Ahi, const __nv_bfloat16* __restrict__ Alo,
    const __nv_bfloat16* __restrict__ Bhi_all, const __nv_bfloat16* __restrict__ Blo_all,
    const float* __restrict__ bias_q, const float* __restrict__ bias_k,
    const float* __restrict__ bias_v,
    float* __restrict__ o_direct, int qkv_mode)
{
    __shared__ __nv_bfloat16 sA[2][CTA_M][ASTR];   // [hi/lo][row][k]
    __shared__ __nv_bfloat16 sB[2][CTA_N][ASTR];   // [hi/lo][n][k]

    int tid = threadIdx.x;
    int wid = tid >> 5, lane = tid & 31;
    int wm = wid >> 2, wn = wid & 3;               // warp grid 2x4
    int m0 = blockIdx.x * CTA_M;
    int n0 = blockIdx.y * CTA_N;
    int which = blockIdx.z;
    const __nv_bfloat16* Bhi = Bhi_all + (size_t)which * CC * CC;
    const __nv_bfloat16* Blo = Blo_all + (size_t)which * CC * CC;
    const float* bias = qkv_mode ? ((which == 0) ? bias_q : (which == 1) ? bias_k : bias_v)
                                 : bias_q;

    // Per-thread copy slots: 8 x uint4 per stage (Ah,Al,Bh,Bl x 2 each)
    const __nv_bfloat16* gsrc[8];
    __nv_bfloat16* sdst[8];
    #pragma unroll
    for (int j = 0; j < 8; j++) {
        int sel = j >> 1;                          // 0 Ah, 1 Al, 2 Bh, 3 Bl
        int idx = ((j & 1) << 8) + tid;            // 0..511
        int row = idx >> 2;
        int c16 = (idx & 3) * 8;                   // bf16 offset of 16B chunk
        const __nv_bfloat16* base =
            (sel == 0) ? Ahi + (size_t)m0 * CC :
            (sel == 1) ? Alo + (size_t)m0 * CC :
            (sel == 2) ? Bhi + (size_t)n0 * CC :
                         Blo + (size_t)n0 * CC;
        gsrc[j] = base + (size_t)row * CC + c16;
        sdst[j] = (sel < 2) ? &sA[sel][row][c16] : &sB[sel - 2][row][c16];
    }

    // ldmatrix base addresses (k16 step adds 32 bytes)
    uint32_t aAddr[2][4], bAddr[2][4];
    {
        int ra = (lane & 15);
        int ca = ((lane >> 4) & 1) * 8;
        int l16 = lane & 15;
        int rb = l16 & 7;
        int cb = ((l16 >> 3) & 1) * 8;
        #pragma unroll
        for (int mf = 0; mf < 4; mf++) {
            aAddr[0][mf] = smem_u32(&sA[0][wm * 64 + mf * 16 + ra][ca]);
            aAddr[1][mf] = smem_u32(&sA[1][wm * 64 + mf * 16 + ra][ca]);
        }
        #pragma unroll
        for (int nf = 0; nf < 4; nf++) {
            bAddr[0][nf] = smem_u32(&sB[0][wn * 32 + nf * 8 + rb][cb]);
            bAddr[1][nf] = smem_u32(&sB[1][wn * 32 + nf * 8 + rb][cb]);
        }
    }

    float acc[4][4][4] = {};

    // Prefetch stage 0
    uint4 pf[8];
    #pragma unroll
    for (int j = 0; j < 8; j++) pf[j] = *(const uint4*)(gsrc[j]);

    for (int s = 0; s < NS; s++) {
        __syncthreads();   // previous compute done before overwrite
        #pragma unroll
        for (int j = 0; j < 8; j++) *(uint4*)(sdst[j]) = pf[j];
        __syncthreads();

        if (s + 1 < NS) {
            #pragma unroll
            for (int j = 0; j < 8; j++)
                pf[j] = *(const uint4*)(gsrc[j] + (s + 1) * KSTG);
        }

        #pragma unroll
        for (int kk = 0; kk < 2; kk++) {
            uint32_t ah[4][4], al[4][4], bh[4][2], bl[4][2];
            #pragma unroll
            for (int mf = 0; mf < 4; mf++) {
                ldsm_x4(ah[mf], aAddr[0][mf] + kk * 32);
                ldsm_x4(al[mf], aAddr[1][mf] + kk * 32);
            }
            #pragma unroll
            for (int nf = 0; nf < 4; nf++) {
                ldsm_x2(bh[nf], bAddr[0][nf] + kk * 32);
                ldsm_x2(bl[nf], bAddr[1][nf] + kk * 32);
            }
            #pragma unroll
            for (int mf = 0; mf < 4; mf++)
                #pragma unroll
                for (int nf = 0; nf < 4; nf++) {
                    mma_bf16(acc[mf][nf], ah[mf], bh[nf]);
                    mma_bf16(acc[mf][nf], ah[mf], bl[nf]);
                    mma_bf16(acc[mf][nf], al[mf], bh[nf]);
                }
        }
    }

    // Epilogue
    int group = lane >> 2, tig = lane & 3;
    #pragma unroll
    for (int mf = 0; mf < 4; mf++) {
        #pragma unroll
        for (int nf = 0; nf < 4; nf++) {
            int ncol = n0 + wn * 32 + nf * 8 + tig * 2;
            float2 bv = *(const float2*)&bias[ncol];
            #pragma unroll
            for (int half = 0; half < 2; half++) {
                int m = m0 + wm * 64 + mf * 16 + group + half * 8;
                float2 o;
                o.x = acc[mf][nf][half * 2 + 0] + bv.x;
                o.y = acc[mf][nf][half * 2 + 1] + bv.y;
                if (qkv_mode) {
                    float* outp = (which == 0) ? g_q : (which == 1) ? g_k : g_v;
                    int b = m >> 11, t = m & (TT - 1);
                    int h = ncol >> 6, d = ncol & 63;
                    *(float2*)&outp[(((size_t)b * HH + h) * TT + t) * HS + d] = o;
                } else {
                    *(float2*)&o_direct[(size_t)m * CC + ncol] = o;
                }
            }
        }
    }
}

// ---------------------------------------------------------------------------
// RoPE apply (in place on g_q, g_k).
// ---------------------------------------------------------------------------
__global__ void rope_apply_kernel() {
    int idx = blockIdx.x * blockDim.x + threadIdx.x;
    if (idx >= BB * HH * TT * 32) return;
    int i  = idx & 31;
    int t  = (idx >> 5) & (TT - 1);
    int bh = idx >> 16;
    float c = g_cos[(t << 5) + i];
    float s = g_sin[(t << 5) + i];
    int base = (bh * TT + t) * HS + i;
    float q1 = g_q[base], q2 = g_q[base + 32];
    g_q[base]      = q1 * c - q2 * s;
    g_q[base + 32] = q2 * c + q1 * s;
    float k1 = g_k[base], k2 = g_k[base + 32];
    g_k[base]      = k1 * c - k2 * s;
    g_k[base + 32] = k2 * c + k1 * s;
}

// ---------------------------------------------------------------------------
// Flash-style causal attention (unchanged from R1 passing version).
// ---------------------------------------------------------------------------
__global__ void __launch_bounds__(256) flash_attn_kernel() {
    __shared__ float Qs[64][65];
    __shared__ float Ks[32][65];
    __shared__ float Vs[32][64];
    __shared__ float Ps[64][33];

    int qb = blockIdx.x;
    int bh = blockIdx.y;
    int q0 = qb * 64;
    const float* Qp = g_q + (size_t)bh * TT * HS;
    const float* Kp = g_k + (size_t)bh * TT * HS;
    const float* Vp = g_v + (size_t)bh * TT * HS;

    int tid = threadIdx.x;
    int tx = tid & 15, ty = tid >> 4;

    #pragma unroll
    for (int r = 0; r < 4; r++) {
        int e4  = tid + r * 256;
        int row = e4 >> 4;
        int c4  = (e4 & 15) * 4;
        float4 qv = *(const float4*)&Qp[(q0 + row) * HS + c4];
        Qs[row][c4 + 0] = qv.x * 0.125f;
        Qs[row][c4 + 1] = qv.y * 0.125f;
        Qs[row][c4 + 2] = qv.z * 0.125f;
        Qs[row][c4 + 3] = qv.w * 0.125f;
    }

    float mrow[4], lrow[4], acc[4][4];
    #pragma unroll
    for (int ii = 0; ii < 4; ii++) {
        mrow[ii] = -1e30f;
        lrow[ii] = 0.f;
        #pragma unroll
        for (int dd = 0; dd < 4; dd++) acc[ii][dd] = 0.f;
    }
    __syncthreads();

    int ktmax = qb * 2 + 1;
    for (int kt = 0; kt <= ktmax; kt++) {
        int k0 = kt * 32;
        #pragma unroll
        for (int r = 0; r < 2; r++) {
            int e4  = tid + r * 256;
            int row = e4 >> 4;
            int c4  = (e4 & 15) * 4;
            float4 kv = *(const float4*)&Kp[(k0 + row) * HS + c4];
            float4 vv = *(const float4*)&Vp[(k0 + row) * HS + c4];
            Ks[row][c4 + 0] = kv.x; Ks[row][c4 + 1] = kv.y;
            Ks[row][c4 + 2] = kv.z; Ks[row][c4 + 3] = kv.w;
            Vs[row][c4 + 0] = vv.x; Vs[row][c4 + 1] = vv.y;
            Vs[row][c4 + 2] = vv.z; Vs[row][c4 + 3] = vv.w;
        }
        __syncthreads();

        float s[4][2];
        #pragma unroll
        for (int ii = 0; ii < 4; ii++) { s[ii][0] = 0.f; s[ii][1] = 0.f; }
        #pragma unroll
        for (int d = 0; d < 64; d++) {
            float av[4], bv2[2];
            #pragma unroll
            for (int ii = 0; ii < 4; ii++) av[ii]  = Qs[ty * 4 + ii][d];
            bv2[0] = Ks[tx * 2 + 0][d];
            bv2[1] = Ks[tx * 2 + 1][d];
            #pragma unroll
            for (int ii = 0; ii < 4; ii++) {
                s[ii][0] += av[ii] * bv2[0];
                s[ii][1] += av[ii] * bv2[1];
            }
        }

        #pragma unroll
        for (int ii = 0; ii < 4; ii++) {
            int qi = q0 + ty * 4 + ii;
            #pragma unroll
            for (int jj = 0; jj < 2; jj++) {
                int kj = k0 + tx * 2 + jj;
                if (kj > qi) s[ii][jj] = -1e30f;
            }
        }

        #pragma unroll
        for (int ii = 0; ii < 4; ii++) {
            float r = fmaxf(s[ii][0], s[ii][1]);
            #pragma unroll
            for (int off = 8; off > 0; off >>= 1)
                r = fmaxf(r, __shfl_xor_sync(0xffffffffu, r, off));
            float mnew = fmaxf(mrow[ii], r);
            float p0 = __expf(s[ii][0] - mnew);
            float p1 = __expf(s[ii][1] - mnew);
            float rs = p0 + p1;
            #pragma unroll
            for (int off = 8; off > 0; off >>= 1)
                rs += __shfl_xor_sync(0xffffffffu, rs, off);
            float f = __expf(mrow[ii] - mnew);
            lrow[ii] = lrow[ii] * f + rs;
            mrow[ii] = mnew;
            #pragma unroll
            for (int dd = 0; dd < 4; dd++) acc[ii][dd] *= f;
            Ps[ty * 4 + ii][tx * 2 + 0] = p0;
            Ps[ty * 4 + ii][tx * 2 + 1] = p1;
        }
        __syncthreads();

        #pragma unroll
        for (int j = 0; j < 32; j++) {
            float pv[4], vv[4];
            #pragma unroll
            for (int ii = 0; ii < 4; ii++) pv[ii] = Ps[ty * 4 + ii][j];
            #pragma unroll
            for (int dd = 0; dd < 4; dd++) vv[dd] = Vs[j][tx * 4 + dd];
            #pragma unroll
            for (int ii = 0; ii < 4; ii++)
                #pragma unroll
                for (int dd = 0; dd < 4; dd++)
                    acc[ii][dd] += pv[ii] * vv[dd];
        }
        __syncthreads();
    }

    int b = bh >> 4, h = bh & 15;
    #pragma unroll
    for (int ii = 0; ii < 4; ii++) {
        int t = q0 + ty * 4 + ii;
        float inv = 1.f / lrow[ii];
        #pragma unroll
        for (int dd = 0; dd < 4; dd++) {
            int col = h * HS + tx * 4 + dd;
            g_y[((size_t)b * TT + t) * CC + col] = acc[ii][dd] * inv;
        }
    }
}

// ---------------------------------------------------------------------------
extern "C" void kernel_launch(void* const* d_in, const int* in_sizes, int n_in,
                              void* d_out, int out_size) {
    const float* qx = (const float*)d_in[0];
    const float* wq = (const float*)d_in[1];
    const float* bq = (const float*)d_in[2];
    const float* wk = (const float*)d_in[3];
    const float* bk = (const float*)d_in[4];
    const float* wv = (const float*)d_in[5];
    const float* bv = (const float*)d_in[6];
    const float* wc = (const float*)d_in[7];
    const float* bc = (const float*)d_in[8];
    float* out = (float*)d_out;

    // device-global pointers for split kernels
    float* p_y;            cudaGetSymbolAddress((void**)&p_y, g_y);
    __nv_bfloat16* p_xhi;  cudaGetSymbolAddress((void**)&p_xhi, g_xhi);
    __nv_bfloat16* p_xlo;  cudaGetSymbolAddress((void**)&p_xlo, g_xlo);
    __nv_bfloat16* p_yhi;  cudaGetSymbolAddress((void**)&p_yhi, g_yhi);
    __nv_bfloat16* p_ylo;  cudaGetSymbolAddress((void**)&p_ylo, g_ylo);
    __nv_bfloat16* p_wthi; cudaGetSymbolAddress((void**)&p_wthi, g_wthi);
    __nv_bfloat16* p_wtlo; cudaGetSymbolAddress((void**)&p_wtlo, g_wtlo);

    rope_tables_kernel<<<(TT * 32 + 255) / 256, 256>>>();

    // Split inputs to bf16 hi/lo
    split_bf16_kernel<<<(MM * CC / 4 + 255) / 256, 256>>>(qx, p_xhi, p_xlo, MM * CC / 4);
    wt_split_kernel<<<dim3(32, 32, 4), dim3(32, 8)>>>(wq, wk, wv, wc);

    // QKV projections on tensor pipe (writes g_q/g_k/g_v in [B,H,T,HS] + bias)
    gemm_mma_kernel<<<dim3(MM / CTA_M, CC / CTA_N, 3), 256>>>(
        p_xhi, p_xlo, p_wthi, p_wtlo, bq, bk, bv, nullptr, 1);

    rope_apply_kernel<<<(BB * HH * TT * 32 + 255) / 256, 256>>>();
    flash_attn_kernel<<<dim3(TT / 64, BB * HH), 256>>>();

    // Output projection on tensor pipe
    split_bf16_kernel<<<(MM * CC / 4 + 255) / 256, 256>>>(p_y, p_yhi, p_ylo, MM * CC / 4);
    gemm_mma_kernel<<<dim3(MM / CTA_M, CC / CTA_N, 1), 256>>>(
        p_yhi, p_ylo, p_wthi + (size_t)3 * CC * CC, p_wtlo + (size_t)3 * CC * CC,
        bc, bc, bc, out, 0);
}

// round 4
// speedup vs baseline: 3.1842x; 1.9794x over previous
#include <cuda_runtime.h>
#include <cuda_bf16.h>
#include <math.h>
#include <stdint.h>

// Problem constants
#define BB 2
#define TT 2048
#define CC 1024
#define HH 16
#define HS 64
#define MM (BB*TT)       // 4096

// GEMM tiling (mma.sync bf16)
#define CTA_M 128
#define CTA_N 128
#define KSTG  32                 // K elems per smem stage
#define NS    (CC/KSTG)          // 32 stages
#define ASTR  40                 // smem row stride in bf16 elems

// Flash tiling
#define FBM 128                  // q rows per CTA
#define FBN 64                   // kv rows per tile
#define FSTR 72                  // padded smem row stride (bf16)
#define FSMEM (36864*2)          // bytes: (2*128 + 4*64) * 72 * 2

// Scratch (device globals: allocation-free)
__device__ float g_q[BB*HH*TT*HS];     // [B,H,T,HS] fp32 (pre-RoPE)
__device__ float g_k[BB*HH*TT*HS];
__device__ float g_v[BB*HH*TT*HS];
__device__ float g_cos[TT*32];
__device__ float g_sin[TT*32];

// bf16 hi/lo split staging
__device__ __nv_bfloat16 g_xhi[MM*CC];
__device__ __nv_bfloat16 g_xlo[MM*CC];
__device__ __nv_bfloat16 g_yhi[MM*CC];
__device__ __nv_bfloat16 g_ylo[MM*CC];
__device__ __nv_bfloat16 g_wthi[4*CC*CC];   // transposed [n][k]: wq,wk,wv,wc
__device__ __nv_bfloat16 g_wtlo[4*CC*CC];
// attention operand splits [B,H,T,HS]
__device__ __nv_bfloat16 g_qhi[BB*HH*TT*HS];
__device__ __nv_bfloat16 g_qlo[BB*HH*TT*HS];
__device__ __nv_bfloat16 g_khi[BB*HH*TT*HS];
__device__ __nv_bfloat16 g_klo[BB*HH*TT*HS];
__device__ __nv_bfloat16 g_vhi[BB*HH*TT*HS];
__device__ __nv_bfloat16 g_vlo[BB*HH*TT*HS];

// ---------------------------------------------------------------------------
// PTX helpers (family-wide sm_80+ only)
// ---------------------------------------------------------------------------
__device__ __forceinline__ uint32_t smem_u32(const void* p) {
    uint32_t a;
    asm("{ .reg .u64 t; cvta.to.shared.u64 t, %1; cvt.u32.u64 %0, t; }" : "=r"(a) : "l"(p));
    return a;
}
__device__ __forceinline__ void ldsm_x4(uint32_t* r, uint32_t addr) {
    asm volatile("ldmatrix.sync.aligned.m8n8.x4.shared.b16 {%0,%1,%2,%3}, [%4];"
        : "=r"(r[0]), "=r"(r[1]), "=r"(r[2]), "=r"(r[3]) : "r"(addr));
}
__device__ __forceinline__ void ldsm_x2(uint32_t* r, uint32_t addr) {
    asm volatile("ldmatrix.sync.aligned.m8n8.x2.shared.b16 {%0,%1}, [%2];"
        : "=r"(r[0]), "=r"(r[1]) : "r"(addr));
}
__device__ __forceinline__ void ldsm_x2t(uint32_t* r, uint32_t addr) {
    asm volatile("ldmatrix.sync.aligned.m8n8.x2.trans.shared.b16 {%0,%1}, [%2];"
        : "=r"(r[0]), "=r"(r[1]) : "r"(addr));
}
__device__ __forceinline__ void mma_bf16(float* c, const uint32_t* a, const uint32_t* b) {
    asm volatile(
        "mma.sync.aligned.m16n8k16.row.col.f32.bf16.bf16.f32 "
        "{%0,%1,%2,%3}, {%4,%5,%6,%7}, {%8,%9}, {%0,%1,%2,%3};"
        : "+f"(c[0]), "+f"(c[1]), "+f"(c[2]), "+f"(c[3])
        : "r"(a[0]), "r"(a[1]), "r"(a[2]), "r"(a[3]), "r"(b[0]), "r"(b[1]));
}
__device__ __forceinline__ uint32_t pack_bf16x2(float lo, float hi) {
    __nv_bfloat162 v = __floats2bfloat162_rn(lo, hi);
    return *(uint32_t*)&v;
}

// ---------------------------------------------------------------------------
// RoPE tables
// ---------------------------------------------------------------------------
__global__ void rope_tables_kernel() {
    int idx = blockIdx.x * blockDim.x + threadIdx.x;   // t*32 + i
    if (idx >= TT * 32) return;
    int i = idx & 31;
    int t = idx >> 5;
    double invf_d = exp(-(double)i * (log(10000.0) / 32.0));
    float invf = (float)invf_d;
    float arg_f = (float)t * invf;
    double s, c;
    sincos((double)arg_f, &s, &c);
    g_cos[idx] = (float)c;
    g_sin[idx] = (float)s;
}

// ---------------------------------------------------------------------------
// fp32 -> bf16 hi/lo split, vectorized x4
// ---------------------------------------------------------------------------
__global__ void split_bf16_kernel(const float* __restrict__ src,
                                  __nv_bfloat16* __restrict__ hi,
                                  __nv_bfloat16* __restrict__ lo, int n4) {
    int i = blockIdx.x * blockDim.x + threadIdx.x;
    if (i >= n4) return;
    float4 v = ((const float4*)src)[i];
    float vv[4] = {v.x, v.y, v.z, v.w};
    __nv_bfloat162 h01, h23, l01, l23;
    __nv_bfloat16 h[4], l[4];
    #pragma unroll
    for (int j = 0; j < 4; j++) {
        h[j] = __float2bfloat16(vv[j]);
        l[j] = __float2bfloat16(vv[j] - __bfloat162float(h[j]));
    }
    h01.x = h[0]; h01.y = h[1]; h23.x = h[2]; h23.y = h[3];
    l01.x = l[0]; l01.y = l[1]; l23.x = l[2]; l23.y = l[3];
    ((__nv_bfloat162*)hi)[2*i]   = h01;
    ((__nv_bfloat162*)hi)[2*i+1] = h23;
    ((__nv_bfloat162*)lo)[2*i]   = l01;
    ((__nv_bfloat162*)lo)[2*i+1] = l23;
}

// ---------------------------------------------------------------------------
// Weight transpose + split: Wt[n][k] = split(W[k][n]); grid.z selects matrix
// ---------------------------------------------------------------------------
__global__ void wt_split_kernel(const float* __restrict__ wq, const float* __restrict__ wk,
                                const float* __restrict__ wv, const float* __restrict__ wc) {
    __shared__ float tile[32][33];
    int wsel = blockIdx.z;
    const float* W = (wsel == 0) ? wq : (wsel == 1) ? wk : (wsel == 2) ? wv : wc;
    __nv_bfloat16* Whi = g_wthi + (size_t)wsel * CC * CC;
    __nv_bfloat16* Wlo = g_wtlo + (size_t)wsel * CC * CC;
    int k0 = blockIdx.x * 32, n0 = blockIdx.y * 32;
    int tx = threadIdx.x, ty = threadIdx.y;   // (32,8)
    #pragma unroll
    for (int j = 0; j < 4; j++)
        tile[ty + 8*j][tx] = W[(size_t)(k0 + ty + 8*j) * CC + n0 + tx];
    __syncthreads();
    #pragma unroll
    for (int j = 0; j < 4; j++) {
        float v = tile[tx][ty + 8*j];
        __nv_bfloat16 h = __float2bfloat16(v);
        __nv_bfloat16 l = __float2bfloat16(v - __bfloat162float(h));
        size_t o = (size_t)(n0 + ty + 8*j) * CC + k0 + tx;
        Whi[o] = h;
        Wlo[o] = l;
    }
}

// ---------------------------------------------------------------------------
// mma.sync bf16 GEMM with 3-MMA split (unchanged from R3 passing version)
// ---------------------------------------------------------------------------
__global__ void __launch_bounds__(256, 1) gemm_mma_kernel(
    const __nv_bfloat16* __restrict__ Ahi, const __nv_bfloat16* __restrict__ Alo,
    const __nv_bfloat16* __restrict__ Bhi_all, const __nv_bfloat16* __restrict__ Blo_all,
    const float* __restrict__ bias_q, const float* __restrict__ bias_k,
    const float* __restrict__ bias_v,
    float* __restrict__ o_direct, int qkv_mode)
{
    __shared__ __nv_bfloat16 sA[2][CTA_M][ASTR];
    __shared__ __nv_bfloat16 sB[2][CTA_N][ASTR];

    int tid = threadIdx.x;
    int wid = tid >> 5, lane = tid & 31;
    int wm = wid >> 2, wn = wid & 3;
    int m0 = blockIdx.x * CTA_M;
    int n0 = blockIdx.y * CTA_N;
    int which = blockIdx.z;
    const __nv_bfloat16* Bhi = Bhi_all + (size_t)which * CC * CC;
    const __nv_bfloat16* Blo = Blo_all + (size_t)which * CC * CC;
    const float* bias = qkv_mode ? ((which == 0) ? bias_q : (which == 1) ? bias_k : bias_v)
                                 : bias_q;

    const __nv_bfloat16* gsrc[8];
    __nv_bfloat16* sdst[8];
    #pragma unroll
    for (int j = 0; j < 8; j++) {
        int sel = j >> 1;
        int idx = ((j & 1) << 8) + tid;
        int row = idx >> 2;
        int c16 = (idx & 3) * 8;
        const __nv_bfloat16* base =
            (sel == 0) ? Ahi + (size_t)m0 * CC :
            (sel == 1) ? Alo + (size_t)m0 * CC :
            (sel == 2) ? Bhi + (size_t)n0 * CC :
                         Blo + (size_t)n0 * CC;
        gsrc[j] = base + (size_t)row * CC + c16;
        sdst[j] = (sel < 2) ? &sA[sel][row][c16] : &sB[sel - 2][row][c16];
    }

    uint32_t aAddr[2][4], bAddr[2][4];
    {
        int ra = (lane & 15);
        int ca = ((lane >> 4) & 1) * 8;
        int l16 = lane & 15;
        int rb = l16 & 7;
        int cb = ((l16 >> 3) & 1) * 8;
        #pragma unroll
        for (int mf = 0; mf < 4; mf++) {
            aAddr[0][mf] = smem_u32(&sA[0][wm * 64 + mf * 16 + ra][ca]);
            aAddr[1][mf] = smem_u32(&sA[1][wm * 64 + mf * 16 + ra][ca]);
        }
        #pragma unroll
        for (int nf = 0; nf < 4; nf++) {
            bAddr[0][nf] = smem_u32(&sB[0][wn * 32 + nf * 8 + rb][cb]);
            bAddr[1][nf] = smem_u32(&sB[1][wn * 32 + nf * 8 + rb][cb]);
        }
    }

    float acc[4][4][4] = {};

    uint4 pf[8];
    #pragma unroll
    for (int j = 0; j < 8; j++) pf[j] = *(const uint4*)(gsrc[j]);

    for (int s = 0; s < NS; s++) {
        __syncthreads();
        #pragma unroll
        for (int j = 0; j < 8; j++) *(uint4*)(sdst[j]) = pf[j];
        __syncthreads();

        if (s + 1 < NS) {
            #pragma unroll
            for (int j = 0; j < 8; j++)
                pf[j] = *(const uint4*)(gsrc[j] + (s + 1) * KSTG);
        }

        #pragma unroll
        for (int kk = 0; kk < 2; kk++) {
            uint32_t ah[4][4], al[4][4], bh[4][2], bl[4][2];
            #pragma unroll
            for (int mf = 0; mf < 4; mf++) {
                ldsm_x4(ah[mf], aAddr[0][mf] + kk * 32);
                ldsm_x4(al[mf], aAddr[1][mf] + kk * 32);
            }
            #pragma unroll
            for (int nf = 0; nf < 4; nf++) {
                ldsm_x2(bh[nf], bAddr[0][nf] + kk * 32);
                ldsm_x2(bl[nf], bAddr[1][nf] + kk * 32);
            }
            #pragma unroll
            for (int mf = 0; mf < 4; mf++)
                #pragma unroll
                for (int nf = 0; nf < 4; nf++) {
                    mma_bf16(acc[mf][nf], ah[mf], bh[nf]);
                    mma_bf16(acc[mf][nf], ah[mf], bl[nf]);
                    mma_bf16(acc[mf][nf], al[mf], bh[nf]);
                }
        }
    }

    int group = lane >> 2, tig = lane & 3;
    #pragma unroll
    for (int mf = 0; mf < 4; mf++) {
        #pragma unroll
        for (int nf = 0; nf < 4; nf++) {
            int ncol = n0 + wn * 32 + nf * 8 + tig * 2;
            float2 bv = *(const float2*)&bias[ncol];
            #pragma unroll
            for (int half = 0; half < 2; half++) {
                int m = m0 + wm * 64 + mf * 16 + group + half * 8;
                float2 o;
                o.x = acc[mf][nf][half * 2 + 0] + bv.x;
                o.y = acc[mf][nf][half * 2 + 1] + bv.y;
                if (qkv_mode) {
                    float* outp = (which == 0) ? g_q : (which == 1) ? g_k : g_v;
                    int b = m >> 11, t = m & (TT - 1);
                    int h = ncol >> 6, d = ncol & 63;
                    *(float2*)&outp[(((size_t)b * HH + h) * TT + t) * HS + d] = o;
                } else {
                    *(float2*)&o_direct[(size_t)m * CC + ncol] = o;
                }
            }
        }
    }
}

// ---------------------------------------------------------------------------
// RoPE apply + bf16 hi/lo split. Q scaled by 1/sqrt(HS)=0.125 before split.
// Reads g_q/g_k fp32, writes qhi/qlo/khi/klo bf16.
// ---------------------------------------------------------------------------
__global__ void rope_split_kernel() {
    int idx = blockIdx.x * blockDim.x + threadIdx.x;
    if (idx >= BB * HH * TT * 32) return;
    int i  = idx & 31;
    int t  = (idx >> 5) & (TT - 1);
    int bh = idx >> 16;
    float c = g_cos[(t << 5) + i];
    float s = g_sin[(t << 5) + i];
    int base = (bh * TT + t) * HS + i;

    float q1 = g_q[base], q2 = g_q[base + 32];
    float qa = (q1 * c - q2 * s) * 0.125f;
    float qb = (q2 * c + q1 * s) * 0.125f;
    __nv_bfloat16 h;
    h = __float2bfloat16(qa); g_qhi[base]      = h; g_qlo[base]      = __float2bfloat16(qa - __bfloat162float(h));
    h = __float2bfloat16(qb); g_qhi[base + 32] = h; g_qlo[base + 32] = __float2bfloat16(qb - __bfloat162float(h));

    float k1 = g_k[base], k2 = g_k[base + 32];
    float ka = k1 * c - k2 * s;
    float kb = k2 * c + k1 * s;
    h = __float2bfloat16(ka); g_khi[base]      = h; g_klo[base]      = __float2bfloat16(ka - __bfloat162float(h));
    h = __float2bfloat16(kb); g_khi[base + 32] = h; g_klo[base + 32] = __float2bfloat16(kb - __bfloat162float(h));
}

// ---------------------------------------------------------------------------
// Tensor-core flash attention (causal), bf16 split operands, fp32 softmax.
// CTA: 128 q-rows, 8 warps (16 rows each), KV tile 64. Epilogue writes
// g_yhi/g_ylo bf16 split in [B,T,C] layout (ready for output GEMM).
// ---------------------------------------------------------------------------
__global__ void __launch_bounds__(256) flash_tc_kernel() {
    extern __shared__ __nv_bfloat16 fsm[];
    __nv_bfloat16* sQh = fsm;                 // 128 x 72
    __nv_bfloat16* sQl = fsm + 9216;          // 128 x 72
    __nv_bfloat16* sKh = fsm + 18432;         // 64 x 72
    __nv_bfloat16* sKl = fsm + 23040;
    __nv_bfloat16* sVh = fsm + 27648;
    __nv_bfloat16* sVl = fsm + 32256;

    int qb = blockIdx.x;
    int bh = blockIdx.y;
    int q0 = qb * FBM;
    size_t hbase = (size_t)bh * TT * HS;

    int tid = threadIdx.x;
    int wid = tid >> 5, lane = tid & 31;
    int g = lane >> 2, tig = lane & 3;

    // ---- stage Q tile (128x64 x hi/lo) ----
    {
        const __nv_bfloat16* Qh = g_qhi + hbase + (size_t)q0 * HS;
        const __nv_bfloat16* Ql = g_qlo + hbase + (size_t)q0 * HS;
        #pragma unroll
        for (int j = 0; j < 4; j++) {
            int c = tid + j * 256;            // 0..1023
            int row = c >> 3;
            int col8 = (c & 7) * 8;
            *(uint4*)&sQh[row * FSTR + col8] = *(const uint4*)&Qh[row * HS + col8];
            *(uint4*)&sQl[row * FSTR + col8] = *(const uint4*)&Ql[row * HS + col8];
        }
    }

    // K/V copy slots: 8 x uint4 per tile
    const __nv_bfloat16* kvsrc[8];
    __nv_bfloat16* kvdst[8];
    {
        const __nv_bfloat16* bases[4] = {
            g_khi + hbase, g_klo + hbase, g_vhi + hbase, g_vlo + hbase };
        __nv_bfloat16* sb[4] = { sKh, sKl, sVh, sVl };
        #pragma unroll
        for (int j = 0; j < 8; j++) {
            int c = tid + j * 256;            // 0..2047
            int sel = c >> 9;
            int cc = c & 511;
            int row = cc >> 3;
            int col8 = (cc & 7) * 8;
            kvsrc[j] = bases[sel] + row * HS + col8;
            kvdst[j] = sb[sel] + row * FSTR + col8;
        }
    }

    // ldmatrix base addresses
    uint32_t aQh = smem_u32(&sQh[(wid * 16 + (lane & 15)) * FSTR + ((lane >> 4) & 1) * 8]);
    uint32_t aQl = aQh + 9216 * 2;
    uint32_t aKh = smem_u32(&sKh[(lane & 7) * FSTR + ((lane >> 3) & 1) * 8]);
    uint32_t aKl = aKh + 4608 * 2;
    uint32_t aVh = smem_u32(&sVh[(lane & 15) * FSTR]);
    uint32_t aVl = aVh + 4608 * 2;

    float m0 = -1e30f, m1 = -1e30f, l0 = 0.f, l1 = 0.f;
    float acc_o[8][4] = {};
    int rw0 = q0 + wid * 16;                  // warp's min row
    int rq0 = rw0 + g, rq1 = rq0 + 8;

    int ktmax = (q0 + FBM - 1) >> 6;

    uint4 pf[8];
    #pragma unroll
    for (int j = 0; j < 8; j++) pf[j] = *(const uint4*)(kvsrc[j]);

    for (int kt = 0; kt <= ktmax; kt++) {
        __syncthreads();
        #pragma unroll
        for (int j = 0; j < 8; j++) *(uint4*)(kvdst[j]) = pf[j];
        __syncthreads();
        if (kt < ktmax) {
            #pragma unroll
            for (int j = 0; j < 8; j++)
                pf[j] = *(const uint4*)(kvsrc[j] + (size_t)(kt + 1) * FBN * HS);
        }
        int k0 = kt * FBN;

        // ---- S = Q K^T (3-MMA split) ----
        float s[8][4] = {};
        #pragma unroll
        for (int kc = 0; kc < 4; kc++) {
            uint32_t qh[4], ql[4];
            ldsm_x4(qh, aQh + kc * 32);
            ldsm_x4(ql, aQl + kc * 32);
            #pragma unroll
            for (int nf = 0; nf < 8; nf++) {
                uint32_t kh2[2], kl2[2];
                ldsm_x2(kh2, aKh + nf * 1152 + kc * 32);
                ldsm_x2(kl2, aKl + nf * 1152 + kc * 32);
                mma_bf16(s[nf], qh, kh2);
                mma_bf16(s[nf], qh, kl2);
                mma_bf16(s[nf], ql, kh2);
            }
        }

        // ---- causal mask (diagonal tiles only) ----
        if (k0 + FBN - 1 > rw0) {
            #pragma unroll
            for (int nf = 0; nf < 8; nf++) {
                int c0 = k0 + nf * 8 + tig * 2;
                if (c0     > rq0) s[nf][0] = -1e30f;
                if (c0 + 1 > rq0) s[nf][1] = -1e30f;
                if (c0     > rq1) s[nf][2] = -1e30f;
                if (c0 + 1 > rq1) s[nf][3] = -1e30f;
            }
        }

        // ---- online softmax (fp32 on fragments) ----
        float mx0 = -1e30f, mx1 = -1e30f;
        #pragma unroll
        for (int nf = 0; nf < 8; nf++) {
            mx0 = fmaxf(mx0, fmaxf(s[nf][0], s[nf][1]));
            mx1 = fmaxf(mx1, fmaxf(s[nf][2], s[nf][3]));
        }
        #pragma unroll
        for (int off = 1; off <= 2; off <<= 1) {
            mx0 = fmaxf(mx0, __shfl_xor_sync(0xffffffffu, mx0, off));
            mx1 = fmaxf(mx1, __shfl_xor_sync(0xffffffffu, mx1, off));
        }
        float mn0 = fmaxf(m0, mx0), mn1 = fmaxf(m1, mx1);
        float sum0 = 0.f, sum1 = 0.f;
        #pragma unroll
        for (int nf = 0; nf < 8; nf++) {
            s[nf][0] = __expf(s[nf][0] - mn0);
            s[nf][1] = __expf(s[nf][1] - mn0);
            s[nf][2] = __expf(s[nf][2] - mn1);
            s[nf][3] = __expf(s[nf][3] - mn1);
            sum0 += s[nf][0] + s[nf][1];
            sum1 += s[nf][2] + s[nf][3];
        }
        #pragma unroll
        for (int off = 1; off <= 2; off <<= 1) {
            sum0 += __shfl_xor_sync(0xffffffffu, sum0, off);
            sum1 += __shfl_xor_sync(0xffffffffu, sum1, off);
        }
        float f0 = __expf(m0 - mn0), f1 = __expf(m1 - mn1);
        l0 = l0 * f0 + sum0; m0 = mn0;
        l1 = l1 * f1 + sum1; m1 = mn1;
        #pragma unroll
        for (int nf = 0; nf < 8; nf++) {
            acc_o[nf][0] *= f0; acc_o[nf][1] *= f0;
            acc_o[nf][2] *= f1; acc_o[nf][3] *= f1;
        }

        // ---- O += P V (split P = Ph + Pl; V pre-split) ----
        #pragma unroll
        for (int jc = 0; jc < 4; jc++) {
            // A fragments from S accumulators (layout identity)
            uint32_t aPh[4], aPl[4];
            {
                float p00 = s[2*jc][0],   p01 = s[2*jc][1];
                float p10 = s[2*jc][2],   p11 = s[2*jc][3];
                float p20 = s[2*jc+1][0], p21 = s[2*jc+1][1];
                float p30 = s[2*jc+1][2], p31 = s[2*jc+1][3];
                aPh[0] = pack_bf16x2(p00, p01);
                aPh[1] = pack_bf16x2(p10, p11);
                aPh[2] = pack_bf16x2(p20, p21);
                aPh[3] = pack_bf16x2(p30, p31);
                __nv_bfloat162 b0 = *(__nv_bfloat162*)&aPh[0];
                __nv_bfloat162 b1 = *(__nv_bfloat162*)&aPh[1];
                __nv_bfloat162 b2 = *(__nv_bfloat162*)&aPh[2];
                __nv_bfloat162 b3 = *(__nv_bfloat162*)&aPh[3];
                aPl[0] = pack_bf16x2(p00 - __bfloat162float(b0.x), p01 - __bfloat162float(b0.y));
                aPl[1] = pack_bf16x2(p10 - __bfloat162float(b1.x), p11 - __bfloat162float(b1.y));
                aPl[2] = pack_bf16x2(p20 - __bfloat162float(b2.x), p21 - __bfloat162float(b2.y));
                aPl[3] = pack_bf16x2(p30 - __bfloat162float(b3.x), p31 - __bfloat162float(b3.y));
            }
            #pragma unroll
            for (int nf = 0; nf < 8; nf++) {
                uint32_t vh2[2], vl2[2];
                ldsm_x2t(vh2, aVh + jc * 2304 + nf * 16);
                ldsm_x2t(vl2, aVl + jc * 2304 + nf * 16);
                mma_bf16(acc_o[nf], aPh, vh2);
                mma_bf16(acc_o[nf], aPh, vl2);
                mma_bf16(acc_o[nf], aPl, vh2);
            }
        }
    }

    // ---- epilogue: O/l -> g_yhi/g_ylo bf16 split, [B,T,C] ----
    {
        float inv0 = 1.f / l0, inv1 = 1.f / l1;
        int b = bh >> 4, h = bh & 15;
        size_t rb0 = ((size_t)b * TT + rq0) * CC;
        size_t rb1 = ((size_t)b * TT + rq1) * CC;
        #pragma unroll
        for (int nf = 0; nf < 8; nf++) {
            int col = h * HS + nf * 8 + tig * 2;
            float v0 = acc_o[nf][0] * inv0, v1 = acc_o[nf][1] * inv0;
            float v2 = acc_o[nf][2] * inv1, v3 = acc_o[nf][3] * inv1;
            __nv_bfloat162 hh, ll;
            hh.x = __float2bfloat16(v0); hh.y = __float2bfloat16(v1);
            ll.x = __float2bfloat16(v0 - __bfloat162float(hh.x));
            ll.y = __float2bfloat16(v1 - __bfloat162float(hh.y));
            *(__nv_bfloat162*)&g_yhi[rb0 + col] = hh;
            *(__nv_bfloat162*)&g_ylo[rb0 + col] = ll;
            hh.x = __float2bfloat16(v2); hh.y = __float2bfloat16(v3);
            ll.x = __float2bfloat16(v2 - __bfloat162float(hh.x));
            ll.y = __float2bfloat16(v3 - __bfloat162float(hh.y));
            *(__nv_bfloat162*)&g_yhi[rb1 + col] = hh;
            *(__nv_bfloat162*)&g_ylo[rb1 + col] = ll;
        }
    }
}

// ---------------------------------------------------------------------------
extern "C" void kernel_launch(void* const* d_in, const int* in_sizes, int n_in,
                              void* d_out, int out_size) {
    const float* qx = (const float*)d_in[0];
    const float* wq = (const float*)d_in[1];
    const float* bq = (const float*)d_in[2];
    const float* wk = (const float*)d_in[3];
    const float* bk = (const float*)d_in[4];
    const float* wv = (const float*)d_in[5];
    const float* bv = (const float*)d_in[6];
    const float* wc = (const float*)d_in[7];
    const float* bc = (const float*)d_in[8];
    float* out = (float*)d_out;

    // device-global pointers
    float* p_v;            cudaGetSymbolAddress((void**)&p_v, g_v);
    __nv_bfloat16* p_xhi;  cudaGetSymbolAddress((void**)&p_xhi, g_xhi);
    __nv_bfloat16* p_xlo;  cudaGetSymbolAddress((void**)&p_xlo, g_xlo);
    __nv_bfloat16* p_yhi;  cudaGetSymbolAddress((void**)&p_yhi, g_yhi);
    __nv_bfloat16* p_ylo;  cudaGetSymbolAddress((void**)&p_ylo, g_ylo);
    __nv_bfloat16* p_wthi; cudaGetSymbolAddress((void**)&p_wthi, g_wthi);
    __nv_bfloat16* p_wtlo; cudaGetSymbolAddress((void**)&p_wtlo, g_wtlo);
    __nv_bfloat16* p_vhi;  cudaGetSymbolAddress((void**)&p_vhi, g_vhi);
    __nv_bfloat16* p_vlo;  cudaGetSymbolAddress((void**)&p_vlo, g_vlo);

    cudaFuncSetAttribute(flash_tc_kernel,
                         cudaFuncAttributeMaxDynamicSharedMemorySize, FSMEM);

    rope_tables_kernel<<<(TT * 32 + 255) / 256, 256>>>();

    // Split inputs to bf16 hi/lo
    split_bf16_kernel<<<(MM * CC / 4 + 255) / 256, 256>>>(qx, p_xhi, p_xlo, MM * CC / 4);
    wt_split_kernel<<<dim3(32, 32, 4), dim3(32, 8)>>>(wq, wk, wv, wc);

    // QKV projections (fp32 out g_q/g_k/g_v in [B,H,T,HS] + bias)
    gemm_mma_kernel<<<dim3(MM / CTA_M, CC / CTA_N, 3), 256>>>(
        p_xhi, p_xlo, p_wthi, p_wtlo, bq, bk, bv, nullptr, 1);

    // RoPE + split Q/K; split V
    rope_split_kernel<<<(BB * HH * TT * 32 + 255) / 256, 256>>>();
    split_bf16_kernel<<<(BB * HH * TT * HS / 4 + 255) / 256, 256>>>(
        p_v, p_vhi, p_vlo, BB * HH * TT * HS / 4);

    // Tensor-core flash attention -> g_yhi/g_ylo
    flash_tc_kernel<<<dim3(TT / FBM, BB * HH), 256, FSMEM>>>();

    // Output projection -> d_out
    gemm_mma_kernel<<<dim3(MM / CTA_M, CC / CTA_N, 1), 256>>>(
        p_yhi, p_ylo, p_wthi + (size_t)3 * CC * CC, p_wtlo + (size_t)3 * CC * CC,
        bc, bc, bc, out, 0);
}